// round 5
// baseline (speedup 1.0000x reference)
#include <cuda_runtime.h>
#include <cuda_bf16.h>
#include <math.h>
#include <stdint.h>

// ---------------- problem constants ----------------
#define CDIM   96
#define DD     32
#define HH     64
#define WWD    64
#define BATCH  2
#define SP     131072
#define NTOK   (BATCH * SP)
#define NWIN   2048
#define NHEAD  4
#define HDIM   24
#define NWT    64

// ---------------- device scratch ----------------
__device__ float         g_x2 [(size_t)NTOK * CDIM];   // residual, SPATIAL token-major
__device__ __nv_bfloat16 g_hn [(size_t)NTOK * CDIM];   // LN2 out, SPATIAL token-major
// bf16 weights
__device__ __nv_bfloat16 g_wqkv[288 * 96];
__device__ __nv_bfloat16 g_wproj[96 * 96];
__device__ __nv_bfloat16 g_wfc1[384 * 96];
__device__ __nv_bfloat16 g_wfc2[96 * 384];

__device__ __forceinline__ uint32_t packbf(float a, float b) {
    __nv_bfloat162 h = __floats2bfloat162_rn(a, b);
    return *reinterpret_cast<uint32_t*>(&h);
}
__device__ __forceinline__ float2 unpackbf(uint32_t u) {
    return __bfloat1622float2(*reinterpret_cast<const __nv_bfloat162*>(&u));
}

__global__ void k_wconv(const float* __restrict__ a, const float* __restrict__ b,
                        const float* __restrict__ c, const float* __restrict__ d)
{
    int i = blockIdx.x * 256 + threadIdx.x;
    if (i < 27648)            g_wqkv[i]          = __float2bfloat16_rn(a[i]);
    else if (i < 36864)       g_wproj[i - 27648] = __float2bfloat16_rn(b[i - 27648]);
    else if (i < 73728)       g_wfc1[i - 36864]  = __float2bfloat16_rn(c[i - 36864]);
    else if (i < 110592)      g_wfc2[i - 73728]  = __float2bfloat16_rn(d[i - 73728]);
}

// ---------------- mma helpers (M=64, K=96, pitch 52 u32) ----------------
__device__ __forceinline__ void mma_bf16(float c[4], const uint32_t a[4], const uint32_t b[2]) {
    asm volatile(
        "mma.sync.aligned.m16n8k16.row.col.f32.bf16.bf16.f32 "
        "{%0,%1,%2,%3}, {%4,%5,%6,%7}, {%8,%9}, {%0,%1,%2,%3};\n"
        : "+f"(c[0]), "+f"(c[1]), "+f"(c[2]), "+f"(c[3])
        : "r"(a[0]), "r"(a[1]), "r"(a[2]), "r"(a[3]), "r"(b[0]), "r"(b[1]));
}

// warp layout: wm = warp>>1 (M 16-row slab), wn = warp&1 (N 48-col half)
__device__ __forceinline__ void mma64(const uint32_t* As, const uint32_t* Bs,
                                      float acc[6][4], int g, int t4, int wm, int wn)
{
    #pragma unroll
    for (int ks = 0; ks < 6; ks++) {
        int k8 = ks * 8;
        uint32_t af[4];
        int rb = wm * 16;
        af[0] = As[(rb + g    ) * 52 + k8 + t4    ];
        af[1] = As[(rb + g + 8) * 52 + k8 + t4    ];
        af[2] = As[(rb + g    ) * 52 + k8 + t4 + 4];
        af[3] = As[(rb + g + 8) * 52 + k8 + t4 + 4];
        uint32_t bf[6][2];
        #pragma unroll
        for (int nt = 0; nt < 6; nt++) {
            int nb = wn * 48 + nt * 8;
            bf[nt][0] = Bs[(nb + g) * 52 + k8 + t4    ];
            bf[nt][1] = Bs[(nb + g) * 52 + k8 + t4 + 4];
        }
        #pragma unroll
        for (int nt = 0; nt < 6; nt++)
            mma_bf16(acc[nt], af, bf[nt]);
    }
}

__device__ __forceinline__ void stage_B96(const __nv_bfloat16* Wb, int bn, uint32_t* Bs, int tid) {
    for (int i = tid; i < 96 * 12; i += 256) {
        int row = i / 12, q = i - row * 12;
        ((uint4*)&Bs[row * 52])[q] = ((const uint4*)(Wb + (size_t)(bn + row) * 96))[q];
    }
}

// ---------------- smem offsets ----------------
#define MG_AS    0        // u32[64*52] = 13312B
#define MG_BS    13312    // u32[96*52] = 19968B
#define MG_QKVS  33280    // u32[64*144] = 36864B ; reused as xs f32[64*97]
#define MG_BCOL  70144    // f32[4*344]
#define MG_GTOK  75648
#define MG_SMU   75904
#define MG_SRS   76160
#define MG_SGA   76416
#define MG_SBA   76800
#define MG_SG2   77184
#define MG_SB2   77568
#define MG_SIZE  77952

// ============================================================
// MEGAKERNEL: one window per block.
// LN1+roll+gather -> qkv GEMM -> attention -> proj GEMM ->
// residual + LN2 -> write x2 (f32) / hn (bf16) spatial-major.
// ============================================================
__global__ void __launch_bounds__(256)
k_mega(const float* __restrict__ x,
       const float* __restrict__ n1g, const float* __restrict__ n1b,
       const float* __restrict__ qbias, const float* __restrict__ rpb,
       const float* __restrict__ pbias,
       const float* __restrict__ n2g, const float* __restrict__ n2b)
{
    extern __shared__ char smem[];
    uint32_t* As   = (uint32_t*)(smem + MG_AS);
    uint32_t* Bs   = (uint32_t*)(smem + MG_BS);
    uint32_t* qkvs = (uint32_t*)(smem + MG_QKVS);
    float*    xs   = (float*)(smem + MG_QKVS);
    float*    bcol = (float*)(smem + MG_BCOL);
    int*      gtok = (int*)(smem + MG_GTOK);
    float*    smu  = (float*)(smem + MG_SMU);
    float*    srs  = (float*)(smem + MG_SRS);
    float*    sgA  = (float*)(smem + MG_SGA);
    float*    sbA  = (float*)(smem + MG_SBA);
    float*    sg2  = (float*)(smem + MG_SG2);
    float*    sb2  = (float*)(smem + MG_SB2);

    int tid  = threadIdx.x;
    int widx = blockIdx.x;
    int b    = widx >> 11;
    int wi   = widx & 2047;
    int wd = wi >> 8, wh = (wi >> 4) & 15, ww = wi & 15;

    if (tid < 96) {
        sgA[tid] = n1g[tid]; sbA[tid] = n1b[tid];
        sg2[tid] = n2g[tid]; sb2[tid] = n2b[tid];
    }
    for (int i = tid; i < 4 * 343; i += 256) {
        int hph = i / 343, r = i - hph * 343;
        bcol[hph * 344 + r] = rpb[r * NHEAD + hph];
    }
    if (tid < 64) {
        int id = tid >> 4, ih = (tid >> 2) & 3, iw = tid & 3;
        int da = wd * 4 + id, ha = wh * 4 + ih, wa = ww * 4 + iw;
        int rd = (da < DD  - 4) ? 0 : ((da < DD  - 2) ? 1 : 2);
        int rh = (ha < HH  - 4) ? 0 : ((ha < HH  - 2) ? 1 : 2);
        int rw = (wa < WWD - 4) ? 0 : ((wa < WWD - 2) ? 1 : 2);
        gtok[tid] = rd * 9 + rh * 3 + rw;
    }

    // ---- phase 1: gather x + pack bf16 into As
    int t     = tid & 63;
    int slice = tid >> 6;
    int tD = (wd * 4 + (t >> 4) + 2) & 31;
    int tH = (wh * 4 + ((t >> 2) & 3) + 2) & 63;
    int tW = (ww * 4 + (t & 3) + 2) & 63;
    int spoff = tD * 4096 + tH * 64 + tW;
    size_t xbase = ((size_t)b * 96) * SP + spoff;

    #pragma unroll
    for (int p = 0; p < 12; p++) {
        int c = slice * 24 + 2 * p;
        float v0 = x[xbase + (size_t)c * SP];
        float v1 = x[xbase + (size_t)(c + 1) * SP];
        As[t * 52 + slice * 12 + p] = packbf(v0, v1);
    }
    __syncthreads();

    // ---- LN1 in place (one thread per token)
    if (tid < 64) {
        uint32_t* row = As + tid * 52;
        float s = 0.f, ss = 0.f;
        #pragma unroll
        for (int p = 0; p < 48; p++) {
            float2 f = unpackbf(row[p]);
            s += f.x + f.y; ss += f.x * f.x + f.y * f.y;
        }
        float mean = s * (1.f / 96.f);
        float rstd = rsqrtf(ss * (1.f / 96.f) - mean * mean + 1e-5f);
        #pragma unroll
        for (int p = 0; p < 48; p++) {
            float2 f = unpackbf(row[p]);
            f.x = (f.x - mean) * rstd * sgA[2 * p] + sbA[2 * p];
            f.y = (f.y - mean) * rstd * sgA[2 * p + 1] + sbA[2 * p + 1];
            row[p] = packbf(f.x, f.y);
        }
    }
    __syncthreads();

    int warp = tid >> 5, lane = tid & 31, g = lane >> 2, t4 = lane & 3;
    int wm = warp >> 1, wn = warp & 1;

    // ---- phase 2: qkv GEMM (3 N-tiles) -> qkvs smem
    for (int bt = 0; bt < 3; bt++) {
        stage_B96(g_wqkv, bt * 96, Bs, tid);
        __syncthreads();
        float acc[6][4];
        #pragma unroll
        for (int j = 0; j < 6; j++)
            #pragma unroll
            for (int r = 0; r < 4; r++) acc[j][r] = 0.f;
        mma64(As, Bs, acc, g, t4, wm, wn);
        #pragma unroll
        for (int nt = 0; nt < 6; nt++) {
            int ncol = wn * 48 + nt * 8 + t4 * 2;
            int u    = bt * 48 + (ncol >> 1);
            #pragma unroll
            for (int half = 0; half < 2; half++) {
                int row = wm * 16 + g + half * 8;
                float v0 = acc[nt][half * 2 + 0] + qbias[bt * 96 + ncol];
                float v1 = acc[nt][half * 2 + 1] + qbias[bt * 96 + ncol + 1];
                qkvs[row * 144 + u] = packbf(v0, v1);
            }
        }
        __syncthreads();
    }

    // ---- phase 3: attention (4 heads x 64 rows, all smem)
    {
        int hh  = tid >> 6;
        int tok = tid & 63;
        const uint32_t* qrow = qkvs + tok * 144 + hh * 12;
        float q[HDIM];
        #pragma unroll
        for (int p = 0; p < 12; p++) {
            float2 f = unpackbf(qrow[p]);
            q[2 * p    ] = f.x * 0.2041241452319315f;
            q[2 * p + 1] = f.y * 0.2041241452319315f;
        }
        int id = tok >> 4, ih = (tok >> 2) & 3, iw = tok & 3;
        int mygrp = gtok[tok];
        const float* bch = bcol + hh * 344;

        float o[HDIM];
        #pragma unroll
        for (int dd = 0; dd < HDIM; dd++) o[dd] = 0.f;
        float sum = 0.f;

        #pragma unroll 4
        for (int j = 0; j < NWT; j++) {
            const uint32_t* kr = qkvs + j * 144 + 48 + hh * 12;
            float a = 0.f;
            #pragma unroll
            for (int p = 0; p < 12; p++) {
                float2 kf = unpackbf(kr[p]);
                a = fmaf(q[2 * p], kf.x, a);
                a = fmaf(q[2 * p + 1], kf.y, a);
            }
            int jd = j >> 4, jh = (j >> 2) & 3, jw = j & 3;
            a += bch[(id - jd + 3) * 49 + (ih - jh + 3) * 7 + (iw - jw + 3)];
            float e = (gtok[j] == mygrp) ? __expf(a) : 0.f;
            sum += e;
            const uint32_t* vr = qkvs + j * 144 + 96 + hh * 12;
            #pragma unroll
            for (int p = 0; p < 12; p++) {
                float2 vf = unpackbf(vr[p]);
                o[2 * p    ] = fmaf(e, vf.x, o[2 * p    ]);
                o[2 * p + 1] = fmaf(e, vf.y, o[2 * p + 1]);
            }
        }
        float inv = 1.f / sum;
        // att out -> As (proj GEMM A input)
        #pragma unroll
        for (int p = 0; p < 12; p++)
            As[tok * 52 + hh * 12 + p] = packbf(o[2 * p] * inv, o[2 * p + 1] * inv);
    }

    // ---- phase 4: proj GEMM
    stage_B96(g_wproj, 0, Bs, tid);
    __syncthreads();
    float acc[6][4];
    #pragma unroll
    for (int j = 0; j < 6; j++)
        #pragma unroll
        for (int r = 0; r < 4; r++) acc[j][r] = 0.f;
    mma64(As, Bs, acc, g, t4, wm, wn);
    __syncthreads();   // done reading qkvs-region? (attn finished) -> safe to overwrite as xs

    #pragma unroll
    for (int nt = 0; nt < 6; nt++) {
        int cl = wn * 48 + nt * 8 + t4 * 2;
        #pragma unroll
        for (int half = 0; half < 2; half++) {
            int rl = wm * 16 + g + half * 8;
            xs[rl * 97 + cl    ] = acc[nt][half * 2 + 0] + pbias[cl];
            xs[rl * 97 + cl + 1] = acc[nt][half * 2 + 1] + pbias[cl + 1];
        }
    }
    __syncthreads();

    // ---- phase 5: residual gather + LN2 + writes
    #pragma unroll
    for (int p = 0; p < 12; p++) {
        int c = slice * 24 + 2 * p;
        xs[t * 97 + c    ] += x[xbase + (size_t)c * SP];
        xs[t * 97 + c + 1] += x[xbase + (size_t)(c + 1) * SP];
    }
    __syncthreads();

    if (tid < 64) {
        const float* row = xs + tid * 97;
        float s = 0.f, ss = 0.f;
        #pragma unroll
        for (int c = 0; c < 96; c++) { float v = row[c]; s += v; ss += v * v; }
        float mean = s * (1.f / 96.f);
        smu[tid] = mean;
        srs[tid] = rsqrtf(ss * (1.f / 96.f) - mean * mean + 1e-5f);
    }
    __syncthreads();

    {
        int tt = tid >> 2, qq = tid & 3;
        int iD = (wd * 4 + (tt >> 4) + 2) & 31;
        int iH = (wh * 4 + ((tt >> 2) & 3) + 2) & 63;
        int iW = (ww * 4 + (tt & 3) + 2) & 63;
        size_t row = ((size_t)b * SP + iD * 4096 + iH * 64 + iW) * 96;
        float mu = smu[tt], rs = srs[tt];
        #pragma unroll
        for (int p = 0; p < 6; p++) {
            int c = qq * 24 + p * 4;
            float v0 = xs[tt * 97 + c    ];
            float v1 = xs[tt * 97 + c + 1];
            float v2 = xs[tt * 97 + c + 2];
            float v3 = xs[tt * 97 + c + 3];
            *(float4*)&g_x2[row + c] = make_float4(v0, v1, v2, v3);
            uint2 ho;
            ho.x = packbf((v0 - mu) * rs * sg2[c    ] + sb2[c    ],
                          (v1 - mu) * rs * sg2[c + 1] + sb2[c + 1]);
            ho.y = packbf((v2 - mu) * rs * sg2[c + 2] + sb2[c + 2],
                          (v3 - mu) * rs * sg2[c + 3] + sb2[c + 3]);
            *(uint2*)&g_hn[row + c] = ho;
        }
    }
}

// ============================================================
// Fused MLP: fc1 + GELU (smem intermediate) + fc2 + residual + transpose out
// 64-token tiles, grid NTOK/64.
// ============================================================
#define ML_AS   0
#define ML_BS   13312
#define ML_M1   33280        // 4 chunks x u32[64*52] = 53248B
#define ML_SIZE 86528

__global__ void __launch_bounds__(256)
k_mlp(const float* __restrict__ f1bias, const float* __restrict__ f2bias,
      float* __restrict__ out)
{
    extern __shared__ char smem[];
    uint32_t* As  = (uint32_t*)(smem + ML_AS);
    uint32_t* Bs  = (uint32_t*)(smem + ML_BS);
    float*    sout = (float*)(smem + ML_AS);   // reused after mainloops

    int tid = threadIdx.x;
    size_t bm = (size_t)blockIdx.x * 64;
    int warp = tid >> 5, lane = tid & 31, g = lane >> 2, t4 = lane & 3;
    int wm = warp >> 1, wn = warp & 1;

    // stage A (hn rows, contiguous)
    for (int i = tid; i < 64 * 12; i += 256) {
        int row = i / 12, q = i - row * 12;
        ((uint4*)&As[row * 52])[q] = ((const uint4*)(g_hn + (bm + row) * 96))[q];
    }

    // fc1 + gelu -> m1s chunks
    for (int bt = 0; bt < 4; bt++) {
        stage_B96(g_wfc1, bt * 96, Bs, tid);
        __syncthreads();
        float acc[6][4];
        #pragma unroll
        for (int j = 0; j < 6; j++)
            #pragma unroll
            for (int r = 0; r < 4; r++) acc[j][r] = 0.f;
        mma64(As, Bs, acc, g, t4, wm, wn);
        uint32_t* m1 = (uint32_t*)(smem + ML_M1 + bt * 13312);
        #pragma unroll
        for (int nt = 0; nt < 6; nt++) {
            int ncol = wn * 48 + nt * 8 + t4 * 2;
            #pragma unroll
            for (int half = 0; half < 2; half++) {
                int row = wm * 16 + g + half * 8;
                float v0 = acc[nt][half * 2 + 0] + f1bias[bt * 96 + ncol];
                float v1 = acc[nt][half * 2 + 1] + f1bias[bt * 96 + ncol + 1];
                v0 = 0.5f * v0 * (1.f + erff(v0 * 0.70710678118654752f));
                v1 = 0.5f * v1 * (1.f + erff(v1 * 0.70710678118654752f));
                m1[row * 52 + (ncol >> 1)] = packbf(v0, v1);
            }
        }
        __syncthreads();
    }

    // fc2: accumulate over 4 K-chunks from smem m1
    float acc2[6][4];
    #pragma unroll
    for (int j = 0; j < 6; j++)
        #pragma unroll
        for (int r = 0; r < 4; r++) acc2[j][r] = 0.f;

    for (int kc = 0; kc < 4; kc++) {
        for (int i = tid; i < 96 * 12; i += 256) {
            int row = i / 12, q = i - row * 12;
            ((uint4*)&Bs[row * 52])[q] =
                ((const uint4*)(g_wfc2 + (size_t)row * 384 + kc * 96))[q];
        }
        __syncthreads();
        const uint32_t* m1 = (const uint32_t*)(smem + ML_M1 + kc * 13312);
        mma64(m1, Bs, acc2, g, t4, wm, wn);
        __syncthreads();
    }

    // epilogue: + bias + x2 residual, transpose to channel-major out
    int b   = (int)(bm >> 17);
    int sp0 = (int)(bm & (SP - 1));

    #pragma unroll
    for (int p = 0; p < 2; p++) {
        if (wn == p) {
            #pragma unroll
            for (int nt = 0; nt < 6; nt++) {
                int cl = nt * 8 + t4 * 2;
                #pragma unroll
                for (int half = 0; half < 2; half++) {
                    int rl = wm * 16 + g + half * 8;
                    float2 xv = *(const float2*)&g_x2[(bm + rl) * 96 + p * 48 + cl];
                    sout[(cl    ) * 68 + rl] = acc2[nt][half * 2 + 0] + f2bias[p * 48 + cl    ] + xv.x;
                    sout[(cl + 1) * 68 + rl] = acc2[nt][half * 2 + 1] + f2bias[p * 48 + cl + 1] + xv.y;
                }
            }
        }
        __syncthreads();
        for (int i = tid; i < 48 * 64; i += 256) {
            int c = i >> 6, tk = i & 63;
            out[((size_t)b * 96 + p * 48 + c) * SP + sp0 + tk] = sout[c * 68 + tk];
        }
        __syncthreads();
    }
}

// ============================================================
// launch
// ============================================================
extern "C" void kernel_launch(void* const* d_in, const int* in_sizes, int n_in,
                              void* d_out, int out_size)
{
    const float* x    = (const float*)d_in[0];
    const float* n1g  = (const float*)d_in[1];
    const float* n1b  = (const float*)d_in[2];
    const float* qkvw = (const float*)d_in[3];
    const float* qkvb = (const float*)d_in[4];
    const float* rpb  = (const float*)d_in[5];
    const float* pw   = (const float*)d_in[6];
    const float* pb   = (const float*)d_in[7];
    const float* n2g  = (const float*)d_in[8];
    const float* n2b  = (const float*)d_in[9];
    const float* f1w  = (const float*)d_in[10];
    const float* f1b  = (const float*)d_in[11];
    const float* f2w  = (const float*)d_in[12];
    const float* f2b  = (const float*)d_in[13];
    float* out = (float*)d_out;

    static int smem_set = 0;
    if (!smem_set) {
        cudaFuncSetAttribute(k_mega, cudaFuncAttributeMaxDynamicSharedMemorySize, MG_SIZE);
        cudaFuncSetAttribute(k_mlp,  cudaFuncAttributeMaxDynamicSharedMemorySize, ML_SIZE);
        smem_set = 1;
    }

    k_wconv<<<432, 256>>>(qkvw, pw, f1w, f2w);
    k_mega<<<NTOK / 64, 256, MG_SIZE>>>(x, n1g, n1b, qkvb, rpb, pb, n2g, n2b);
    k_mlp <<<NTOK / 64, 256, ML_SIZE>>>(f1b, f2b, out);
}